// round 16
// baseline (speedup 1.0000x reference)
#include <cuda_runtime.h>
#include <cuda_fp16.h>
#include <math.h>
#include <stdint.h>

#define NN 8192
#define DF 256
#define KT 64                 // j per stage (two 32-j sub-stages)
#define KSPLIT 2
#define KQ (NN / KSPLIT)      // 4096
#define NSTG (KQ / KT)        // 64 stages
#define YSCALE 2048.0f
#define MROWS 64              // CTA M tile (2 CTAs/SM)

// smem layout: A double-buffered (2 stages x 2 kh x 4KB), B ring of 3 (32KB each)
#define OFF_A(s, kh)  (((s) & 1) * 8192 + (kh) * 4096)
#define OFF_B(s, kh)  (16384 + ((s) % 3) * 32768 + (kh) * 16384)
#define SMEM_BYTES (16384 + 3 * 32768)   // 114688 = 112KB -> 2 CTAs/SM (224KB <= 228KB)

// ---------------- device scratch ----------------
__device__ float g_h2[NN];
__device__ float g_u[NN];
__device__ __half g_Yh[(size_t)DF * NN];   // (u*x*2048)^T fp16 [feature][j], j-perm per 32-block
__device__ float g_num[(size_t)KSPLIT * NN * DF];
__device__ float g_den[(size_t)KSPLIT * NN];

// j-permutation within a 32 block (verified R3-R15):
// makes B fragments one LDS.128 and A fragment pairs one LDS.64
__host__ __device__ __forceinline__ int permj(int r) {
    int g = r >> 4, p = (r & 15) >> 1, o = r & 1;
    int q = p & 3, slot = (p >> 2) + 2 * g;
    return 8 * q + 2 * slot + o;
}

// no volatile / no memory clobber — pure register op, ptxas schedules freely
__device__ __forceinline__ void mma_fp16(float* c, const uint32_t* a, uint32_t b0, uint32_t b1) {
    asm("mma.sync.aligned.m16n8k16.row.col.f32.f16.f16.f32 "
        "{%0,%1,%2,%3}, {%4,%5,%6,%7}, {%8,%9}, {%0,%1,%2,%3};"
        : "+f"(c[0]), "+f"(c[1]), "+f"(c[2]), "+f"(c[3])
        : "r"(a[0]), "r"(a[1]), "r"(a[2]), "r"(a[3]), "r"(b0), "r"(b1));
}

__device__ __forceinline__ uint32_t smem_u32(const void* p) {
    uint32_t a;
    asm("{ .reg .u64 t; cvta.to.shared.u64 t, %1; cvt.u32.u64 %0, t; }" : "=r"(a) : "l"(p));
    return a;
}

// streaming (evict-first) int4 load — keeps adj from evicting Y^T in L2
__device__ __forceinline__ int4 ldcs_int4(const int4* p) {
    int4 v;
    asm("ld.global.cs.v4.s32 {%0,%1,%2,%3}, [%4];"
        : "=r"(v.x), "=r"(v.y), "=r"(v.z), "=r"(v.w) : "l"(p));
    return v;
}
__device__ __forceinline__ void stcs_f2(float* p, float2 v) {
    asm volatile("st.global.cs.v2.f32 [%0], {%1,%2};" :: "l"(p), "f"(v.x), "f"(v.y));
}

// ---------------------------------------------------------------------------
// Prep 1: h2[j] = input[j,:] . A[0:D]   (h1 term cancels in softmax)
// ---------------------------------------------------------------------------
__global__ void k_h2(const float* __restrict__ input, const float* __restrict__ A) {
    int warp = (blockIdx.x * blockDim.x + threadIdx.x) >> 5;
    int lane = threadIdx.x & 31;
    if (warp >= NN) return;
    const float* row = input + (size_t)warp * DF;
    float v = 0.f;
#pragma unroll
    for (int t = 0; t < DF / 32; t++) v += row[lane + t * 32] * A[lane + t * 32];
#pragma unroll
    for (int o = 16; o; o >>= 1) v += __shfl_xor_sync(0xffffffffu, v, o);
    if (lane == 0) g_h2[warp] = v;
}

// ---------------------------------------------------------------------------
// Prep 2: global max + u[j] = exp(h2[j]-g)   (row max cancels in the ratio)
// ---------------------------------------------------------------------------
__global__ void k_u() {
    __shared__ float smax[1024];
    int tid = threadIdx.x;
    float m = -INFINITY;
    for (int j = tid; j < NN; j += 1024) m = fmaxf(m, g_h2[j]);
    smax[tid] = m;
    __syncthreads();
#pragma unroll
    for (int s = 512; s; s >>= 1) {
        if (tid < s) smax[tid] = fmaxf(smax[tid], smax[tid + s]);
        __syncthreads();
    }
    float g = smax[0];
    for (int j = tid; j < NN; j += 1024) g_u[j] = expf(g_h2[j] - g);
}

// ---------------------------------------------------------------------------
// Prep 3: Y^T = (u*x*2048)^T fp16, j-permuted within 32-blocks
// ---------------------------------------------------------------------------
__global__ void k_y(const float* __restrict__ input) {
    __shared__ float tile[32][33];
    int j0 = blockIdx.x * 32, k0 = blockIdx.y * 32;
    int tx = threadIdx.x, ty = threadIdx.y;
#pragma unroll
    for (int r = 0; r < 32; r += 8) {
        int j = j0 + ty + r;
        tile[ty + r][tx] = input[(size_t)j * DF + k0 + tx] * (g_u[j] * YSCALE);
    }
    __syncthreads();
#pragma unroll
    for (int r = 0; r < 32; r += 8) {
        int k = k0 + ty + r;
        g_Yh[(size_t)k * NN + j0 + permj(tx)] = __float2half(tile[tx][ty + r]);
    }
}

// ---------------------------------------------------------------------------
// Main: num = adj @ Y (fp16 mma.sync, fp32 acc); den = adj.u scalar
// grid 256: ks = bid&1 (K split 2), row block = (bid>>1)*64
// 256 threads (8 warps, 1M x 8N, warp tile 64x32), 2 CTAs/SM
// B ring depth 3, prefetch distance 2 (wait_group 2 -> B gets 2 stages slack)
// ---------------------------------------------------------------------------
__global__ __launch_bounds__(256, 2) void k_main(const int* __restrict__ adj) {
    extern __shared__ char smem[];
    const uint32_t sb = smem_u32(smem);
    const int tid = threadIdx.x;
    const int wid = tid >> 5, lane = tid & 31;
    const int wn = wid;                            // 8 N-warps, warp tile 64x32
    const int rA = lane >> 2, qA = lane & 3;
    const int ks = blockIdx.x & (KSPLIT - 1);
    const int row0 = (blockIdx.x >> 1) * MROWS;
    const int jb = ks * KQ;
    const int ar = tid >> 2, aq = tid & 3;         // A staging: row ar (0..63), quarter aq

    float acc[4][4][4];
#pragma unroll
    for (int mf = 0; mf < 4; mf++)
#pragma unroll
        for (int nf = 0; nf < 4; nf++)
#pragma unroll
            for (int c = 0; c < 4; c++) acc[mf][nf][c] = 0.f;
    float den = 0.f;

    auto loadB = [&](int s) {
        int j0 = jb + s * KT;
#pragma unroll
        for (int kh = 0; kh < 2; kh++) {
            uint32_t base = sb + OFF_B(s, kh);
#pragma unroll
            for (int i = 0; i < 4; i++) {
                int id = i * 256 + tid;             // 0..1023
                int row = id >> 2;
                int ch = id & 3;
                const __half* src = g_Yh + (size_t)row * NN + j0 + kh * 32 + ch * 8;
                uint32_t dst = base + row * 64 + ch * 16;
                asm volatile("cp.async.cg.shared.global [%0], [%1], 16;" :: "r"(dst), "l"(src));
            }
        }
        asm volatile("cp.async.commit_group;" ::: "memory");
    };
    // thread gathers j's 8aq..8aq+7 (2 streaming LDG.128)
    auto loadAdjH = [&](int s, int kh, int4* r) {
        const int4* base =
            (const int4*)(adj + (size_t)(row0 + ar) * NN + jb + s * KT + kh * 32 + aq * 8);
        r[0] = ldcs_int4(base);
        r[1] = ldcs_int4(base + 1);
    };
    auto storeAH = [&](int s, int kh, const int4* r) {
        char* arow = smem + OFF_A(s, kh) + ar * 64;
        const float4* up = (const float4*)(g_u + jb + s * KT + kh * 32 + aq * 8);
        float4 u0 = up[0], u1 = up[1];
        den += (r[0].x > 0 ? u0.x : 0.f) + (r[0].y > 0 ? u0.y : 0.f)
             + (r[0].z > 0 ? u0.z : 0.f) + (r[0].w > 0 ? u0.w : 0.f)
             + (r[1].x > 0 ? u1.x : 0.f) + (r[1].y > 0 ? u1.y : 0.f)
             + (r[1].z > 0 ? u1.z : 0.f) + (r[1].w > 0 ? u1.w : 0.f);
#pragma unroll
        for (int c = 0; c < 2; c++) {
            uint32_t v0 = (r[c].x > 0 ? 0x3C00u : 0u) | (r[c].y > 0 ? 0x3C000000u : 0u);
            uint32_t v1 = (r[c].z > 0 ? 0x3C00u : 0u) | (r[c].w > 0 ? 0x3C000000u : 0u);
            int P0 = 4 * aq + 2 * c;
#pragma unroll
            for (int e = 0; e < 2; e++) {
                int P = P0 + e;
                int g = P >> 3, pp = P & 7;
                int byte = 16 * (pp & 3) + 4 * ((pp >> 2) + 2 * g);
                *(uint32_t*)(arow + byte) = e ? v1 : v0;
            }
        }
    };
    auto computeKH = [&](int s, int kh) {
        const char* As = smem + OFF_A(s, kh);
        const char* Bs = smem + OFF_B(s, kh);
        uint32_t af[4][2][4];
#pragma unroll
        for (int mf = 0; mf < 4; mf++)
#pragma unroll
            for (int g = 0; g < 2; g++) {
                int row = mf * 16 + rA;
                uint2 lo = *(const uint2*)(As + row * 64 + 16 * qA + 8 * g);
                uint2 hi = *(const uint2*)(As + (row + 8) * 64 + 16 * qA + 8 * g);
                af[mf][g][0] = lo.x; af[mf][g][2] = lo.y;
                af[mf][g][1] = hi.x; af[mf][g][3] = hi.y;
            }
#pragma unroll
        for (int h = 0; h < 2; h++) {
            int n0 = wn * 32 + (2 * h) * 8 + rA;
            uint4 b0 = *(const uint4*)(Bs + n0 * 64 + 16 * qA);
            uint4 b1 = *(const uint4*)(Bs + (n0 + 8) * 64 + 16 * qA);
#pragma unroll
            for (int mf = 0; mf < 4; mf++) mma_fp16(acc[mf][2 * h],     af[mf][0], b0.x, b0.y);
#pragma unroll
            for (int mf = 0; mf < 4; mf++) mma_fp16(acc[mf][2 * h + 1], af[mf][0], b1.x, b1.y);
#pragma unroll
            for (int mf = 0; mf < 4; mf++) mma_fp16(acc[mf][2 * h],     af[mf][1], b0.z, b0.w);
#pragma unroll
            for (int mf = 0; mf < 4; mf++) mma_fp16(acc[mf][2 * h + 1], af[mf][1], b1.z, b1.w);
        }
    };

    // ---- prologue: B(0), B(1) in flight; A(0) staged ----
    loadB(0);
    loadB(1);
    {
        int4 t[2];
        loadAdjH(0, 0, t); storeAH(0, 0, t);
        loadAdjH(0, 1, t); storeAH(0, 1, t);
    }

#pragma unroll 1
    for (int s = 0; s < NSTG; s++) {
        __syncthreads();                      // A(s) visible; all warps done with B((s-1)%3)
        if (s + 2 < NSTG) loadB(s + 2);
        else asm volatile("cp.async.commit_group;" ::: "memory");   // keep group count uniform
        asm volatile("cp.async.wait_group 2;" ::: "memory");        // B(s) arrived
        if (s + 1 < NSTG) {
            int4 r[2];
            loadAdjH(s + 1, 0, r);          // LDG latency hidden by computeKH(s,0)
            computeKH(s, 0);
            storeAH(s + 1, 0, r);
            loadAdjH(s + 1, 1, r);          // hidden by computeKH(s,1)
            computeKH(s, 1);
            storeAH(s + 1, 1, r);
        } else {
            computeKH(s, 0);
            computeKH(s, 1);
        }
    }

    // ---- epilogue: split-K partials (streaming stores) ----
#pragma unroll
    for (int mf = 0; mf < 4; mf++) {
        int row = row0 + mf * 16 + rA;
#pragma unroll
        for (int nf = 0; nf < 4; nf++) {
            int col = wn * 32 + nf * 8 + qA * 2;
            float* p0 = g_num + ((size_t)ks * NN + row) * DF + col;
            float* p1 = g_num + ((size_t)ks * NN + row + 8) * DF + col;
            stcs_f2(p0, make_float2(acc[mf][nf][0], acc[mf][nf][1]));
            stcs_f2(p1, make_float2(acc[mf][nf][2], acc[mf][nf][3]));
        }
    }
    den += __shfl_xor_sync(0xffffffffu, den, 1);
    den += __shfl_xor_sync(0xffffffffu, den, 2);
    if ((lane & 3) == 0) g_den[(size_t)ks * NN + row0 + ar] = den;
}

// ---------------------------------------------------------------------------
// Combine split-K partials: out = sum(n) / (YSCALE * sum(d))
// ---------------------------------------------------------------------------
__global__ void k_combine(float* __restrict__ out) {
    int id = blockIdx.x * 256 + threadIdx.x;
    int row = id >> 6, kq = id & 63;
    float4 o = make_float4(0.f, 0.f, 0.f, 0.f);
    float d = 0.f;
#pragma unroll
    for (int p = 0; p < KSPLIT; p++) {
        float4 a = __ldcs((const float4*)(g_num + ((size_t)p * NN + row) * DF) + kq);
        o.x += a.x; o.y += a.y; o.z += a.z; o.w += a.w;
        d += g_den[(size_t)p * NN + row];
    }
    float inv = 1.0f / (YSCALE * d);
    o.x *= inv; o.y *= inv; o.z *= inv; o.w *= inv;
    ((float4*)out)[id] = o;
}

// ---------------------------------------------------------------------------
extern "C" void kernel_launch(void* const* d_in, const int* in_sizes, int n_in,
                              void* d_out, int out_size) {
    const float* input = (const float*)d_in[0];
    const int*   adj   = (const int*)d_in[1];
    const float* A     = (const float*)d_in[2];
    float* out = (float*)d_out;

    cudaFuncSetAttribute(k_main, cudaFuncAttributeMaxDynamicSharedMemorySize, SMEM_BYTES);

    k_h2<<<NN / 8, 256>>>(input, A);
    k_u<<<1, 1024>>>();
    k_y<<<dim3(NN / 32, DF / 32), dim3(32, 8)>>>(input);
    k_main<<<KSPLIT * (NN / MROWS), 256, SMEM_BYTES>>>(adj);
    k_combine<<<(NN * DF / 4) / 256, 256>>>(out);
}

// round 17
// speedup vs baseline: 1.1391x; 1.1391x over previous
#include <cuda_runtime.h>
#include <cuda_fp16.h>
#include <math.h>
#include <stdint.h>

#define NN 8192
#define DF 256
#define KT 64                 // j per stage (two 32-j sub-stages)
#define KSPLIT 2
#define KQ (NN / KSPLIT)      // 4096
#define NSTG (KQ / KT)        // 64 stages
#define YSCALE 2048.0f
#define MROWS 64              // CTA M tile (2 CTAs/SM)

// per-buffer smem layout: A sub-buffers (2 x 4KB) then B sub-buffers (2 x 16KB)
#define OFF_A0  0
#define OFF_A1  4096
#define OFF_B0  8192
#define OFF_B1  24576
#define BUFSZ   40960
#define SMEM_BYTES (2 * BUFSZ)   // 81920

// ---------------- device scratch ----------------
__device__ float g_h2[NN];
__device__ float g_u[NN];
__device__ __half g_Yh[(size_t)DF * NN];   // (u*x*2048)^T fp16 [feature][j], j-perm per 32-block
__device__ float g_num[(size_t)KSPLIT * NN * DF];
__device__ float g_den[(size_t)KSPLIT * NN];

// j-permutation within a 32 block (verified R3-R16):
// makes B fragments one LDS.128 and A fragment pairs one LDS.64
__host__ __device__ __forceinline__ int permj(int r) {
    int g = r >> 4, p = (r & 15) >> 1, o = r & 1;
    int q = p & 3, slot = (p >> 2) + 2 * g;
    return 8 * q + 2 * slot + o;
}

// no volatile / no memory clobber — pure register op, ptxas schedules freely
__device__ __forceinline__ void mma_fp16(float* c, const uint32_t* a, uint32_t b0, uint32_t b1) {
    asm("mma.sync.aligned.m16n8k16.row.col.f32.f16.f16.f32 "
        "{%0,%1,%2,%3}, {%4,%5,%6,%7}, {%8,%9}, {%0,%1,%2,%3};"
        : "+f"(c[0]), "+f"(c[1]), "+f"(c[2]), "+f"(c[3])
        : "r"(a[0]), "r"(a[1]), "r"(a[2]), "r"(a[3]), "r"(b0), "r"(b1));
}

__device__ __forceinline__ uint32_t smem_u32(const void* p) {
    uint32_t a;
    asm("{ .reg .u64 t; cvta.to.shared.u64 t, %1; cvt.u32.u64 %0, t; }" : "=r"(a) : "l"(p));
    return a;
}

// streaming (evict-first) int4 load — keeps adj from evicting Y^T in L2
__device__ __forceinline__ int4 ldcs_int4(const int4* p) {
    int4 v;
    asm("ld.global.cs.v4.s32 {%0,%1,%2,%3}, [%4];"
        : "=r"(v.x), "=r"(v.y), "=r"(v.z), "=r"(v.w) : "l"(p));
    return v;
}
__device__ __forceinline__ void stcs_f2(float* p, float2 v) {
    asm volatile("st.global.cs.v2.f32 [%0], {%1,%2};" :: "l"(p), "f"(v.x), "f"(v.y));
}

// ---------------------------------------------------------------------------
// Prep 1: h2[j] = input[j,:] . A[0:D]   (h1 term cancels in softmax)
// warp per row, lane-contiguous float4: 4 perfectly-coalesced LDG.128 per lane
// ---------------------------------------------------------------------------
__global__ void k_h2(const float* __restrict__ input, const float* __restrict__ A) {
    int warp = (blockIdx.x * blockDim.x + threadIdx.x) >> 5;
    int lane = threadIdx.x & 31;
    if (warp >= NN) return;
    const float4* row = (const float4*)(input + (size_t)warp * DF);
    const float4* a4 = (const float4*)A;
    float4 x0 = row[lane], x1 = row[lane + 32];
    float4 a0 = a4[lane], a1 = a4[lane + 32];
    float v = x0.x * a0.x + x0.y * a0.y + x0.z * a0.z + x0.w * a0.w
            + x1.x * a1.x + x1.y * a1.y + x1.z * a1.z + x1.w * a1.w;
#pragma unroll
    for (int o = 16; o; o >>= 1) v += __shfl_xor_sync(0xffffffffu, v, o);
    if (lane == 0) g_h2[warp] = v;
}

// ---------------------------------------------------------------------------
// Prep 2: global max + u[j] = exp(h2[j]-g)   (row max cancels in the ratio)
// ---------------------------------------------------------------------------
__global__ void k_u() {
    __shared__ float smax[1024];
    int tid = threadIdx.x;
    float m = -INFINITY;
    for (int j = tid; j < NN; j += 1024) m = fmaxf(m, g_h2[j]);
    smax[tid] = m;
    __syncthreads();
#pragma unroll
    for (int s = 512; s; s >>= 1) {
        if (tid < s) smax[tid] = fmaxf(smax[tid], smax[tid + s]);
        __syncthreads();
    }
    float g = smax[0];
    for (int j = tid; j < NN; j += 1024) g_u[j] = expf(g_h2[j] - g);
}

// ---------------------------------------------------------------------------
// Prep 3: Y^T = (u*x*2048)^T fp16, j-permuted within 32-blocks
// ---------------------------------------------------------------------------
__global__ void k_y(const float* __restrict__ input) {
    __shared__ float tile[32][33];
    int j0 = blockIdx.x * 32, k0 = blockIdx.y * 32;
    int tx = threadIdx.x, ty = threadIdx.y;
#pragma unroll
    for (int r = 0; r < 32; r += 8) {
        int j = j0 + ty + r;
        tile[ty + r][tx] = input[(size_t)j * DF + k0 + tx] * (g_u[j] * YSCALE);
    }
    __syncthreads();
#pragma unroll
    for (int r = 0; r < 32; r += 8) {
        int k = k0 + ty + r;
        g_Yh[(size_t)k * NN + j0 + permj(tx)] = __float2half(tile[tx][ty + r]);
    }
}

// ---------------------------------------------------------------------------
// Main: num = adj @ Y (fp16 mma.sync, fp32 acc); den = adj.u scalar
// grid 256: ks = bid&1 (K split 2), row block = (bid>>1)*64
// 256 threads (8 warps, 1M x 8N, warp tile 64x32), 2 CTAs/SM   [R13 verbatim]
// ---------------------------------------------------------------------------
__global__ __launch_bounds__(256, 2) void k_main(const int* __restrict__ adj) {
    extern __shared__ char smem[];
    const uint32_t sb = smem_u32(smem);
    const int tid = threadIdx.x;
    const int wid = tid >> 5, lane = tid & 31;
    const int wn = wid;                            // 8 N-warps, warp tile 64x32
    const int rA = lane >> 2, qA = lane & 3;
    const int ks = blockIdx.x & (KSPLIT - 1);
    const int row0 = (blockIdx.x >> 1) * MROWS;
    const int jb = ks * KQ;
    const int ar = tid >> 2, aq = tid & 3;         // A staging: row ar (0..63), quarter aq

    float acc[4][4][4];
#pragma unroll
    for (int mf = 0; mf < 4; mf++)
#pragma unroll
        for (int nf = 0; nf < 4; nf++)
#pragma unroll
            for (int c = 0; c < 4; c++) acc[mf][nf][c] = 0.f;
    float den = 0.f;

    auto loadB = [&](int s) {
        uint32_t base = sb + (s & 1) * BUFSZ;
        int j0 = jb + s * KT;
#pragma unroll
        for (int kh = 0; kh < 2; kh++) {
#pragma unroll
            for (int i = 0; i < 4; i++) {
                int id = i * 256 + tid;             // 0..1023
                int row = id >> 2;
                int ch = id & 3;
                const __half* src = g_Yh + (size_t)row * NN + j0 + kh * 32 + ch * 8;
                uint32_t dst = base + (kh ? OFF_B1 : OFF_B0) + row * 64 + ch * 16;
                asm volatile("cp.async.cg.shared.global [%0], [%1], 16;" :: "r"(dst), "l"(src));
            }
        }
        asm volatile("cp.async.commit_group;" ::: "memory");
    };
    // thread gathers j's 8aq..8aq+7 (2 streaming LDG.128)
    auto loadAdjH = [&](int s, int kh, int4* r) {
        const int4* base =
            (const int4*)(adj + (size_t)(row0 + ar) * NN + jb + s * KT + kh * 32 + aq * 8);
        r[0] = ldcs_int4(base);
        r[1] = ldcs_int4(base + 1);
    };
    auto storeAH = [&](int s, int kh, const int4* r) {
        char* arow = smem + (s & 1) * BUFSZ + (kh ? OFF_A1 : OFF_A0) + ar * 64;
        const float4* up = (const float4*)(g_u + jb + s * KT + kh * 32 + aq * 8);
        float4 u0 = up[0], u1 = up[1];
        den += (r[0].x > 0 ? u0.x : 0.f) + (r[0].y > 0 ? u0.y : 0.f)
             + (r[0].z > 0 ? u0.z : 0.f) + (r[0].w > 0 ? u0.w : 0.f)
             + (r[1].x > 0 ? u1.x : 0.f) + (r[1].y > 0 ? u1.y : 0.f)
             + (r[1].z > 0 ? u1.z : 0.f) + (r[1].w > 0 ? u1.w : 0.f);
#pragma unroll
        for (int c = 0; c < 2; c++) {
            uint32_t v0 = (r[c].x > 0 ? 0x3C00u : 0u) | (r[c].y > 0 ? 0x3C000000u : 0u);
            uint32_t v1 = (r[c].z > 0 ? 0x3C00u : 0u) | (r[c].w > 0 ? 0x3C000000u : 0u);
            int P0 = 4 * aq + 2 * c;
#pragma unroll
            for (int e = 0; e < 2; e++) {
                int P = P0 + e;
                int g = P >> 3, pp = P & 7;
                int byte = 16 * (pp & 3) + 4 * ((pp >> 2) + 2 * g);
                *(uint32_t*)(arow + byte) = e ? v1 : v0;
            }
        }
    };
    auto computeKH = [&](const char* base, int kh) {
        const char* As = base + (kh ? OFF_A1 : OFF_A0);
        const char* Bs = base + (kh ? OFF_B1 : OFF_B0);
        uint32_t af[4][2][4];
#pragma unroll
        for (int mf = 0; mf < 4; mf++)
#pragma unroll
            for (int g = 0; g < 2; g++) {
                int row = mf * 16 + rA;
                uint2 lo = *(const uint2*)(As + row * 64 + 16 * qA + 8 * g);
                uint2 hi = *(const uint2*)(As + (row + 8) * 64 + 16 * qA + 8 * g);
                af[mf][g][0] = lo.x; af[mf][g][2] = lo.y;
                af[mf][g][1] = hi.x; af[mf][g][3] = hi.y;
            }
#pragma unroll
        for (int h = 0; h < 2; h++) {
            int n0 = wn * 32 + (2 * h) * 8 + rA;
            uint4 b0 = *(const uint4*)(Bs + n0 * 64 + 16 * qA);
            uint4 b1 = *(const uint4*)(Bs + (n0 + 8) * 64 + 16 * qA);
#pragma unroll
            for (int mf = 0; mf < 4; mf++) mma_fp16(acc[mf][2 * h],     af[mf][0], b0.x, b0.y);
#pragma unroll
            for (int mf = 0; mf < 4; mf++) mma_fp16(acc[mf][2 * h + 1], af[mf][0], b1.x, b1.y);
#pragma unroll
            for (int mf = 0; mf < 4; mf++) mma_fp16(acc[mf][2 * h],     af[mf][1], b0.z, b0.w);
#pragma unroll
            for (int mf = 0; mf < 4; mf++) mma_fp16(acc[mf][2 * h + 1], af[mf][1], b1.z, b1.w);
        }
    };

    // ---- prologue: stage 0 fully staged ----
    loadB(0);
    {
        int4 t[2];
        loadAdjH(0, 0, t); storeAH(0, 0, t);
        loadAdjH(0, 1, t); storeAH(0, 1, t);
    }

#pragma unroll 1
    for (int s = 0; s < NSTG; s++) {
        asm volatile("cp.async.wait_group 0;" ::: "memory");   // B(s) arrived
        __syncthreads();                                       // A(s) stores visible
        const char* base = smem + (s & 1) * BUFSZ;
        if (s + 1 < NSTG) {
            loadB(s + 1);
            int4 r[2];
            loadAdjH(s + 1, 0, r);          // LDG latency hidden by computeKH(0)
            computeKH(base, 0);
            storeAH(s + 1, 0, r);
            loadAdjH(s + 1, 1, r);          // hidden by computeKH(1)
            computeKH(base, 1);
            storeAH(s + 1, 1, r);
        } else {
            computeKH(base, 0);
            computeKH(base, 1);
        }
    }

    // ---- epilogue: split-K partials (streaming stores) ----
#pragma unroll
    for (int mf = 0; mf < 4; mf++) {
        int row = row0 + mf * 16 + rA;
#pragma unroll
        for (int nf = 0; nf < 4; nf++) {
            int col = wn * 32 + nf * 8 + qA * 2;
            float* p0 = g_num + ((size_t)ks * NN + row) * DF + col;
            float* p1 = g_num + ((size_t)ks * NN + row + 8) * DF + col;
            stcs_f2(p0, make_float2(acc[mf][nf][0], acc[mf][nf][1]));
            stcs_f2(p1, make_float2(acc[mf][nf][2], acc[mf][nf][3]));
        }
    }
    den += __shfl_xor_sync(0xffffffffu, den, 1);
    den += __shfl_xor_sync(0xffffffffu, den, 2);
    if ((lane & 3) == 0) g_den[(size_t)ks * NN + row0 + ar] = den;
}

// ---------------------------------------------------------------------------
// Combine split-K partials: out = sum(n) / (YSCALE * sum(d))
// ---------------------------------------------------------------------------
__global__ void k_combine(float* __restrict__ out) {
    int id = blockIdx.x * 256 + threadIdx.x;
    int row = id >> 6, kq = id & 63;
    float4 o = make_float4(0.f, 0.f, 0.f, 0.f);
    float d = 0.f;
#pragma unroll
    for (int p = 0; p < KSPLIT; p++) {
        float4 a = __ldcs((const float4*)(g_num + ((size_t)p * NN + row) * DF) + kq);
        o.x += a.x; o.y += a.y; o.z += a.z; o.w += a.w;
        d += g_den[(size_t)p * NN + row];
    }
    float inv = 1.0f / (YSCALE * d);
    o.x *= inv; o.y *= inv; o.z *= inv; o.w *= inv;
    ((float4*)out)[id] = o;
}

// ---------------------------------------------------------------------------
extern "C" void kernel_launch(void* const* d_in, const int* in_sizes, int n_in,
                              void* d_out, int out_size) {
    const float* input = (const float*)d_in[0];
    const int*   adj   = (const int*)d_in[1];
    const float* A     = (const float*)d_in[2];
    float* out = (float*)d_out;

    cudaFuncSetAttribute(k_main, cudaFuncAttributeMaxDynamicSharedMemorySize, SMEM_BYTES);

    k_h2<<<NN / 8, 256>>>(input, A);
    k_u<<<1, 1024>>>();
    k_y<<<dim3(NN / 32, DF / 32), dim3(32, 8)>>>(input);
    k_main<<<KSPLIT * (NN / MROWS), 256, SMEM_BYTES>>>(adj);
    k_combine<<<(NN * DF / 4) / 256, 256>>>(out);
}